// round 13
// baseline (speedup 1.0000x reference)
#include <cuda_runtime.h>
#include <cstdint>

#define N_NODES 10000
#define N_EDGES 160000
#define E_TOT   (N_EDGES + N_NODES)
#define DIM     256
#define HEADS   8
#define CH      32
#define LORA_SCALE 4.0f
#define ATT_SCALE  8.0f
#define NEG_SLOPE  0.2f

// ---------------- tf32 helpers ----------------
__device__ __forceinline__ uint32_t f2tf32(float x) {
    uint32_t r;
    asm("cvt.rna.tf32.f32 %0, %1;" : "=r"(r) : "f"(x));
    return r;
}
__device__ __forceinline__ void mma_tf32(float4& d, uint32_t a0, uint32_t a1, uint32_t a2, uint32_t a3,
                                         uint32_t b0, uint32_t b1) {
    asm("mma.sync.aligned.m16n8k8.row.col.f32.tf32.tf32.f32 "
        "{%0,%1,%2,%3}, {%4,%5,%6,%7}, {%8,%9}, {%0,%1,%2,%3};"
        : "+f"(d.x), "+f"(d.y), "+f"(d.z), "+f"(d.w)
        : "r"(a0), "r"(a1), "r"(a2), "r"(a3), "r"(b0), "r"(b1));
}

// ---------------- device scratch ----------------
__device__ __align__(128) float g_weff0[DIM * DIM];
__device__ __align__(128) float g_weff1[DIM * DIM];
__device__ __align__(128) float g_atts0[DIM];
__device__ __align__(128) float g_attd0[DIM];
__device__ __align__(128) float g_atts1[DIM];
__device__ __align__(128) float g_attd1[DIM];
__device__ __align__(128) float g_xp[N_NODES * DIM];
__device__ __align__(128) float g_act[N_NODES * DIM];
__device__ __align__(128) float g_ssrc[N_NODES * HEADS];
__device__ __align__(128) float g_sdst[N_NODES * HEADS];
__device__ int   g_deg[N_NODES];
__device__ int   g_off[N_NODES + 1];
__device__ int   g_cur[N_NODES];
__device__ int   g_csrc[E_TOT];
__device__ int   g_flag64;   // OR of sampled odd words; 0 iff input is int64

__device__ __forceinline__ int edge_val(const void* ei, long long idx, int is64) {
    if (is64) return (int)((const long long*)ei)[idx];
    return ((const int*)ei)[idx];
}

// ---------------- CSR build ----------------
#define DETECT_N 32768
__global__ void k_detect(const void* ei) {
    int gid = blockIdx.x * blockDim.x + threadIdx.x;   // 40*256 = 10240 threads
    if (gid < N_NODES) g_deg[gid] = 1;                  // self loop pre-counted
    const int* w = (const int*)ei;
    int acc = 0;
    for (int i = gid; i < DETECT_N; i += 10240) acc |= w[2 * i + 1];
#pragma unroll
    for (int o = 16; o; o >>= 1) acc |= __shfl_xor_sync(0xffffffffu, acc, o);
    if ((threadIdx.x & 31) == 0 && acc) atomicOr(&g_flag64, acc);
}

__global__ void k_hist(const void* ei) {
    int is64 = (g_flag64 == 0);
    int e = blockIdx.x * blockDim.x + threadIdx.x;
    if (e < N_EDGES) atomicAdd(&g_deg[edge_val(ei, (long long)N_EDGES + e, is64)], 1);
}

// 1024 threads, 10 nodes each: warp scan + cross-warp scan (proven config)
__global__ void k_scan() {
    __shared__ int warp_sums[32];
    int t = threadIdx.x, lane = t & 31, w = t >> 5;
    int base = t * 10;
    int loc[10];
    int sum = 0;
#pragma unroll
    for (int i = 0; i < 10; i++) {
        int n = base + i;
        int d = (n < N_NODES) ? g_deg[n] : 0;
        loc[i] = sum;
        sum += d;
    }
    int v = sum;
#pragma unroll
    for (int o = 1; o < 32; o <<= 1) {
        int u = __shfl_up_sync(0xffffffffu, v, o);
        if (lane >= o) v += u;
    }
    if (lane == 31) warp_sums[w] = v;
    __syncthreads();
    if (w == 0) {
        int s = warp_sums[lane];
#pragma unroll
        for (int o = 1; o < 32; o <<= 1) {
            int u = __shfl_up_sync(0xffffffffu, s, o);
            if (lane >= o) s += u;
        }
        warp_sums[lane] = s;
    }
    __syncthreads();
    int excl = v - sum + (w ? warp_sums[w - 1] : 0);
#pragma unroll
    for (int i = 0; i < 10; i++) {
        int n = base + i;
        if (n < N_NODES) {
            int o = excl + loc[i];
            g_off[n] = o;
            g_cur[n] = o;
        }
    }
    if (t == 0) g_off[N_NODES] = E_TOT;
}

__global__ void k_scatter(const void* ei) {
    int is64 = (g_flag64 == 0);
    int e = blockIdx.x * blockDim.x + threadIdx.x;
    if (e < N_EDGES) {
        int s = edge_val(ei, e, is64);
        int d = edge_val(ei, (long long)N_EDGES + e, is64);
        g_csrc[atomicAdd(&g_cur[d], 1)] = s;
    } else if (e < E_TOT) {
        int n = e - N_EDGES;
        g_csrc[atomicAdd(&g_cur[n], 1)] = n;
    }
}

// ---------------- fold LoRA into effective weights (one layer, 257 blocks) -------
__global__ void k_prep(const float* __restrict__ W, const float* __restrict__ A,
                       const float* __restrict__ B,
                       const float* __restrict__ as_, const float* __restrict__ ad_,
                       const float* __restrict__ As, const float* __restrict__ Bs,
                       const float* __restrict__ Ad, const float* __restrict__ Bd,
                       float* __restrict__ weff, float* __restrict__ atts,
                       float* __restrict__ attd) {
    int b = blockIdx.x, t = threadIdx.x;
    if (b < DIM) {
        float s = 0.f;
#pragma unroll
        for (int r = 0; r < 8; r++) s += B[b * 8 + r] * A[r * DIM + t];
        weff[b * DIM + t] = W[b * DIM + t] + LORA_SCALE * s;
    } else {
        int c = t & 31;
        float ss = 0.f, sd = 0.f;
#pragma unroll
        for (int r = 0; r < 4; r++) {
            ss += Bs[r] * As[r * CH + c];
            sd += Bd[r] * Ad[r * CH + c];
        }
        atts[t] = as_[t] + ATT_SCALE * ss;
        attd[t] = ad_[t] + ATT_SCALE * sd;
    }
}

// ---------------- 1xTF32 GEMM, fragment-major smem + fused attention scores ------
// Values are tf32-converted ONCE at staging and stored in the exact per-lane
// register layout the mma needs: inner loop = LDS.128 + MMA only.
// A frag (16x8): AsF[fa][lane*4 + v], v = khalf*2 + rowhalf, fa = (warp_m*2+mf)*4+kkidx
// B frag group:  BsF[kkidx*2+warp_n][lane][nf*2 + khalf]  (lane stride 12: conflict-free)
#define BM 128
#define BN 64
#define KC 32
__global__ void __launch_bounds__(256, 2) k_gemm(const float* __restrict__ X,
                                                 const float* __restrict__ Wf,
                                                 float* __restrict__ Y,
                                                 const float* __restrict__ atts,
                                                 const float* __restrict__ attd) {
    __shared__ __align__(16) uint32_t AsF[32][132];     // 32 frags, 128 used + pad
    __shared__ __align__(16) uint32_t BsF[8][32][12];   // 8 frag-groups, 8 used + pad
    const int t = threadIdx.x;
    const int wid = t >> 5, lane = t & 31;
    const int warp_m = wid & 3, warp_n = wid >> 2;
    const int gid = lane >> 2, tq = lane & 3;
    const int m0 = blockIdx.y * BM, n0 = blockIdx.x * BN;
    const int h = blockIdx.x * 2 + warp_n;              // this warp's head
    const float4 z4 = make_float4(0.f, 0.f, 0.f, 0.f);

    // staging assignment: A 2 threads/row (16 k each), B 4 threads/col (8 k each)
    const int a_row = t >> 1, a_seg = t & 1;
    const int b_col = t >> 2, b_q = t & 3;
    const int gmA = m0 + a_row;
    // A-side staging constants
    const int fa_base = ((a_row >> 5) * 2 + ((a_row >> 4) & 1)) * 4;
    const int rowhalf = (a_row >> 3) & 1;
    const int gid_a = a_row & 7;
    // B-side staging constants
    const int wn_s = b_col >> 5;
    const int nf_s = (b_col >> 3) & 3;
    const int gid_b = b_col & 7;

    float4 acc[2][4];
#pragma unroll
    for (int i = 0; i < 2; i++)
#pragma unroll
        for (int j = 0; j < 4; j++) acc[i][j] = z4;

    float4 ra[4], rb[2];

    // ---- prologue: load chunk 0 ----
#pragma unroll
    for (int i = 0; i < 4; i++)
        ra[i] = (gmA < N_NODES) ? *(const float4*)(X + (size_t)gmA * DIM + a_seg * 16 + i * 4) : z4;
    rb[0] = *(const float4*)(Wf + (size_t)(n0 + b_col) * DIM + b_q * 4);
    rb[1] = *(const float4*)(Wf + (size_t)(n0 + b_col) * DIM + 16 + b_q * 4);

#define STAGE_AB()                                                                     \
    {                                                                                  \
        _Pragma("unroll")                                                              \
        for (int i = 0; i < 4; i++) {                                                  \
            int kb = a_seg * 16 + i * 4;                                               \
            uint32_t* dst = &AsF[fa_base + (kb >> 3)][gid_a * 16 + ((kb & 4) >> 1) + rowhalf]; \
            dst[0]  = f2tf32(ra[i].x); dst[4]  = f2tf32(ra[i].y);                      \
            dst[8]  = f2tf32(ra[i].z); dst[12] = f2tf32(ra[i].w);                      \
        }                                                                              \
        _Pragma("unroll")                                                              \
        for (int i = 0; i < 2; i++) {                                                  \
            int kb = i * 16 + b_q * 4;                                                 \
            uint32_t* dst = &BsF[(kb >> 3) * 2 + wn_s][gid_b * 4][nf_s * 2 + ((kb >> 2) & 1)]; \
            float4 v = i ? rb[1] : rb[0];                                              \
            dst[0]  = f2tf32(v.x); dst[12] = f2tf32(v.y);                              \
            dst[24] = f2tf32(v.z); dst[36] = f2tf32(v.w);                              \
        }                                                                              \
    }

    STAGE_AB();
    __syncthreads();

    const int NIT = DIM / KC;   // 8
    for (int it = 0; it < NIT; it++) {
        bool more = (it + 1 < NIT);
        if (more) {
            int k0 = (it + 1) * KC;
#pragma unroll
            for (int i = 0; i < 4; i++)
                ra[i] = (gmA < N_NODES) ? *(const float4*)(X + (size_t)gmA * DIM + k0 + a_seg * 16 + i * 4) : z4;
            rb[0] = *(const float4*)(Wf + (size_t)(n0 + b_col) * DIM + k0 + b_q * 4);
            rb[1] = *(const float4*)(Wf + (size_t)(n0 + b_col) * DIM + k0 + 16 + b_q * 4);
        }
#pragma unroll
        for (int kkidx = 0; kkidx < 4; kkidx++) {
            uint4 bv0 = *(const uint4*)&BsF[kkidx * 2 + warp_n][lane][0];
            uint4 bv1 = *(const uint4*)&BsF[kkidx * 2 + warp_n][lane][4];
#pragma unroll
            for (int mf = 0; mf < 2; mf++) {
                uint4 av = *(const uint4*)&AsF[(warp_m * 2 + mf) * 4 + kkidx][lane * 4];
                mma_tf32(acc[mf][0], av.x, av.y, av.z, av.w, bv0.x, bv0.y);
                mma_tf32(acc[mf][1], av.x, av.y, av.z, av.w, bv0.z, bv0.w);
                mma_tf32(acc[mf][2], av.x, av.y, av.z, av.w, bv1.x, bv1.y);
                mma_tf32(acc[mf][3], av.x, av.y, av.z, av.w, bv1.z, bv1.w);
            }
        }
        __syncthreads();
        if (more) {
            STAGE_AB();
            __syncthreads();
        }
    }

    // ---- epilogue: store Y tile + fused per-head attention scores ----
    const float* ath = atts + h * CH;
    const float* adh = attd + h * CH;
#pragma unroll
    for (int mf = 0; mf < 2; mf++) {
        int r0 = m0 + warp_m * 32 + mf * 16 + gid;
        int r1 = r0 + 8;
        float s0s = 0.f, s0d = 0.f, s1s = 0.f, s1d = 0.f;
#pragma unroll
        for (int nf = 0; nf < 4; nf++) {
            int c = nf * 8 + 2 * tq;
            float4 v = acc[mf][nf];
            float w0s = ath[c], w1s = ath[c + 1];
            float w0d = adh[c], w1d = adh[c + 1];
            s0s += v.x * w0s + v.y * w1s;
            s0d += v.x * w0d + v.y * w1d;
            s1s += v.z * w0s + v.w * w1s;
            s1d += v.z * w0d + v.w * w1d;
            int col = n0 + warp_n * 32 + c;
            if (r0 < N_NODES) *(float2*)(Y + (size_t)r0 * DIM + col) = make_float2(v.x, v.y);
            if (r1 < N_NODES) *(float2*)(Y + (size_t)r1 * DIM + col) = make_float2(v.z, v.w);
        }
#pragma unroll
        for (int o = 1; o < 4; o <<= 1) {
            s0s += __shfl_xor_sync(0xffffffffu, s0s, o);
            s0d += __shfl_xor_sync(0xffffffffu, s0d, o);
            s1s += __shfl_xor_sync(0xffffffffu, s1s, o);
            s1d += __shfl_xor_sync(0xffffffffu, s1d, o);
        }
        if (tq == 0) {
            if (r0 < N_NODES) { g_ssrc[r0 * HEADS + h] = s0s; g_sdst[r0 * HEADS + h] = s0d; }
            if (r1 < N_NODES) { g_ssrc[r1 * HEADS + h] = s1s; g_sdst[r1 * HEADS + h] = s1d; }
        }
    }
}

// ---------------- single-pass softmax + aggregation, 4x unrolled ----------------
template <int MODE>
__global__ void __launch_bounds__(256) k_aggr(const float* __restrict__ xp, float* __restrict__ out) {
    __shared__ float red[256];
    int n = blockIdx.x, t = threadIdx.x;
    int h = t >> 5, lane = t & 31;
    int beg = g_off[n], end = g_off[n + 1];
    float ssrc = g_ssrc[n * HEADS + h];
    const float* __restrict__ xph = xp + h * CH + lane;
    const float* __restrict__ sdh = g_sdst + h;

    float den = 0.f, acc = 0.f;
    int i = beg;
    for (; i + 4 <= end; i += 4) {
        int s0 = g_csrc[i + 0];
        int s1 = g_csrc[i + 1];
        int s2 = g_csrc[i + 2];
        int s3 = g_csrc[i + 3];
        float d0 = sdh[s0 * HEADS], d1 = sdh[s1 * HEADS];
        float d2 = sdh[s2 * HEADS], d3 = sdh[s3 * HEADS];
        float x0 = xph[s0 * DIM], x1 = xph[s1 * DIM];
        float x2 = xph[s2 * DIM], x3 = xph[s3 * DIM];
        float a0 = ssrc + d0, a1 = ssrc + d1, a2 = ssrc + d2, a3 = ssrc + d3;
        a0 = fminf(fmaxf(a0, NEG_SLOPE * a0), 80.f);
        a1 = fminf(fmaxf(a1, NEG_SLOPE * a1), 80.f);
        a2 = fminf(fmaxf(a2, NEG_SLOPE * a2), 80.f);
        a3 = fminf(fmaxf(a3, NEG_SLOPE * a3), 80.f);
        float w0 = __expf(a0), w1 = __expf(a1), w2 = __expf(a2), w3 = __expf(a3);
        den += (w0 + w1) + (w2 + w3);
        acc += w0 * x0 + w1 * x1 + w2 * x2 + w3 * x3;
    }
    for (; i < end; i++) {
        int s = g_csrc[i];
        float a = ssrc + sdh[s * HEADS];
        a = fminf(fmaxf(a, NEG_SLOPE * a), 80.f);
        float w = __expf(a);
        den += w;
        acc += w * xph[s * DIM];
    }
    float r = acc / den;
    if (MODE == 0) {
        out[n * DIM + t] = (r > 0.f) ? r : (__expf(r) - 1.0f);  // ELU
    } else {
        red[t] = r;
        __syncthreads();
        if (t < CH) {
            float s = 0.f;
#pragma unroll
            for (int hh = 0; hh < HEADS; hh++) s += red[hh * CH + t];
            out[n * CH + t] = s * 0.125f;
        }
    }
}

// ---------------- side stream / events (created before harness checkpoints) ------
namespace {
struct StreamInit {
    cudaStream_t s2;
    cudaEvent_t evFork, evJoin;
    StreamInit() {
        cudaStreamCreateWithFlags(&s2, cudaStreamNonBlocking);
        cudaEventCreateWithFlags(&evFork, cudaEventDisableTiming);
        cudaEventCreateWithFlags(&evJoin, cudaEventDisableTiming);
    }
};
StreamInit g_si;
}

// ---------------- host launcher ----------------
// Enqueue order keeps k_gemm as the 4th kernel enqueued (ncu capture slot).
extern "C" void kernel_launch(void* const* d_in, const int* in_sizes, int n_in,
                              void* d_out, int out_size) {
    const float* x  = (const float*)d_in[0];
    const void*  ei = d_in[1];

    float *xp, *act, *weff0, *weff1, *atts0, *attd0, *atts1, *attd1;
    cudaGetSymbolAddress((void**)&xp, g_xp);
    cudaGetSymbolAddress((void**)&act, g_act);
    cudaGetSymbolAddress((void**)&weff0, g_weff0);
    cudaGetSymbolAddress((void**)&weff1, g_weff1);
    cudaGetSymbolAddress((void**)&atts0, g_atts0);
    cudaGetSymbolAddress((void**)&attd0, g_attd0);
    cudaGetSymbolAddress((void**)&atts1, g_atts1);
    cudaGetSymbolAddress((void**)&attd1, g_attd1);

    cudaStream_t s2 = g_si.s2;

    // fork side stream off the (capturing) default stream
    cudaEventRecord(g_si.evFork, 0);
    cudaStreamWaitEvent(s2, g_si.evFork, 0);

    // enqueue #1, #2 (side stream)
    k_prep<<<DIM + 1, DIM, 0, s2>>>(
        (const float*)d_in[11], (const float*)d_in[12], (const float*)d_in[13],
        (const float*)d_in[14], (const float*)d_in[15],
        (const float*)d_in[16], (const float*)d_in[17],
        (const float*)d_in[18], (const float*)d_in[19],
        weff1, atts1, attd1);
    k_detect<<<40, 256, 0, s2>>>(ei);

    dim3 gg(DIM / BN, (N_NODES + BM - 1) / BM);

    // enqueue #3, #4 (main stream) — #4 = k_gemm gets the ncu capture
    k_prep<<<DIM + 1, DIM>>>(
        (const float*)d_in[2], (const float*)d_in[3], (const float*)d_in[4],
        (const float*)d_in[5], (const float*)d_in[6],
        (const float*)d_in[7], (const float*)d_in[8],
        (const float*)d_in[9], (const float*)d_in[10],
        weff0, atts0, attd0);
    k_gemm<<<gg, 256>>>(x, weff0, xp, atts0, attd0);

    // enqueue #5..#7 (side stream, continues after detect)
    k_hist<<<(N_EDGES + 255) / 256, 256, 0, s2>>>(ei);
    k_scan<<<1, 1024, 0, s2>>>();
    k_scatter<<<(E_TOT + 255) / 256, 256, 0, s2>>>(ei);
    cudaEventRecord(g_si.evJoin, s2);

    // join: aggr0 needs CSR; gemm1 needs weff1
    cudaStreamWaitEvent(0, g_si.evJoin, 0);

    k_aggr<0><<<N_NODES, 256>>>(xp, act);
    k_gemm<<<gg, 256>>>(act, weff1, xp, atts1, attd1);
    k_aggr<1><<<N_NODES, 256>>>(xp, (float*)d_out);
}

// round 15
// speedup vs baseline: 1.1549x; 1.1549x over previous
#include <cuda_runtime.h>
#include <cstdint>

#define N_NODES 10000
#define N_EDGES 160000
#define E_TOT   (N_EDGES + N_NODES)
#define DIM     256
#define HEADS   8
#define CH      32
#define LORA_SCALE 4.0f
#define ATT_SCALE  8.0f
#define NEG_SLOPE  0.2f

// ---------------- tf32 / async helpers ----------------
__device__ __forceinline__ uint32_t f2tf32(float x) {
    uint32_t r;
    asm("cvt.rna.tf32.f32 %0, %1;" : "=r"(r) : "f"(x));
    return r;
}
__device__ __forceinline__ void mma_tf32(float4& d, uint32_t a0, uint32_t a1, uint32_t a2, uint32_t a3,
                                         uint32_t b0, uint32_t b1) {
    asm("mma.sync.aligned.m16n8k8.row.col.f32.tf32.tf32.f32 "
        "{%0,%1,%2,%3}, {%4,%5,%6,%7}, {%8,%9}, {%0,%1,%2,%3};"
        : "+f"(d.x), "+f"(d.y), "+f"(d.z), "+f"(d.w)
        : "r"(a0), "r"(a1), "r"(a2), "r"(a3), "r"(b0), "r"(b1));
}
__device__ __forceinline__ void cp16(uint32_t dst_smem, const void* src, uint32_t src_sz) {
    asm volatile("cp.async.ca.shared.global [%0], [%1], 16, %2;"
                 :: "r"(dst_smem), "l"(src), "r"(src_sz));
}
__device__ __forceinline__ void cp_commit() {
    asm volatile("cp.async.commit_group;");
}
template <int N>
__device__ __forceinline__ void cp_wait() {
    asm volatile("cp.async.wait_group %0;" :: "n"(N));
}

// ---------------- device scratch ----------------
__device__ __align__(128) float g_weff0[DIM * DIM];
__device__ __align__(128) float g_weff1[DIM * DIM];
__device__ __align__(128) float g_atts0[DIM];
__device__ __align__(128) float g_attd0[DIM];
__device__ __align__(128) float g_atts1[DIM];
__device__ __align__(128) float g_attd1[DIM];
__device__ __align__(128) float g_xp[N_NODES * DIM];
__device__ __align__(128) float g_act[N_NODES * DIM];
__device__ __align__(128) float g_ssrc[N_NODES * HEADS];
__device__ __align__(128) float g_sdst[N_NODES * HEADS];
__device__ int   g_deg[N_NODES];
__device__ int   g_off[N_NODES + 1];
__device__ int   g_cur[N_NODES];
__device__ int   g_csrc[E_TOT];
__device__ int   g_flag64;   // OR of sampled odd words; 0 iff input is int64

__device__ __forceinline__ int edge_val(const void* ei, long long idx, int is64) {
    if (is64) return (int)((const long long*)ei)[idx];
    return ((const int*)ei)[idx];
}

// ---------------- CSR build ----------------
#define DETECT_N 32768
__global__ void k_detect(const void* ei) {
    int gid = blockIdx.x * blockDim.x + threadIdx.x;   // 40*256 = 10240 threads
    if (gid < N_NODES) g_deg[gid] = 1;                  // self loop pre-counted
    const int* w = (const int*)ei;
    int acc = 0;
    for (int i = gid; i < DETECT_N; i += 10240) acc |= w[2 * i + 1];
#pragma unroll
    for (int o = 16; o; o >>= 1) acc |= __shfl_xor_sync(0xffffffffu, acc, o);
    if ((threadIdx.x & 31) == 0 && acc) atomicOr(&g_flag64, acc);
}

__global__ void k_hist(const void* ei) {
    int is64 = (g_flag64 == 0);
    int e = blockIdx.x * blockDim.x + threadIdx.x;
    if (e < N_EDGES) atomicAdd(&g_deg[edge_val(ei, (long long)N_EDGES + e, is64)], 1);
}

// 1024 threads, 10 nodes each: warp scan + cross-warp scan (proven config)
__global__ void k_scan() {
    __shared__ int warp_sums[32];
    int t = threadIdx.x, lane = t & 31, w = t >> 5;
    int base = t * 10;
    int loc[10];
    int sum = 0;
#pragma unroll
    for (int i = 0; i < 10; i++) {
        int n = base + i;
        int d = (n < N_NODES) ? g_deg[n] : 0;
        loc[i] = sum;
        sum += d;
    }
    int v = sum;
#pragma unroll
    for (int o = 1; o < 32; o <<= 1) {
        int u = __shfl_up_sync(0xffffffffu, v, o);
        if (lane >= o) v += u;
    }
    if (lane == 31) warp_sums[w] = v;
    __syncthreads();
    if (w == 0) {
        int s = warp_sums[lane];
#pragma unroll
        for (int o = 1; o < 32; o <<= 1) {
            int u = __shfl_up_sync(0xffffffffu, s, o);
            if (lane >= o) s += u;
        }
        warp_sums[lane] = s;
    }
    __syncthreads();
    int excl = v - sum + (w ? warp_sums[w - 1] : 0);
#pragma unroll
    for (int i = 0; i < 10; i++) {
        int n = base + i;
        if (n < N_NODES) {
            int o = excl + loc[i];
            g_off[n] = o;
            g_cur[n] = o;
        }
    }
    if (t == 0) g_off[N_NODES] = E_TOT;
}

__global__ void k_scatter(const void* ei) {
    int is64 = (g_flag64 == 0);
    int e = blockIdx.x * blockDim.x + threadIdx.x;
    if (e < N_EDGES) {
        int s = edge_val(ei, e, is64);
        int d = edge_val(ei, (long long)N_EDGES + e, is64);
        g_csrc[atomicAdd(&g_cur[d], 1)] = s;
    } else if (e < E_TOT) {
        int n = e - N_EDGES;
        g_csrc[atomicAdd(&g_cur[n], 1)] = n;
    }
}

// ---------------- fold LoRA into effective weights (one layer, 257 blocks) -------
__global__ void k_prep(const float* __restrict__ W, const float* __restrict__ A,
                       const float* __restrict__ B,
                       const float* __restrict__ as_, const float* __restrict__ ad_,
                       const float* __restrict__ As, const float* __restrict__ Bs,
                       const float* __restrict__ Ad, const float* __restrict__ Bd,
                       float* __restrict__ weff, float* __restrict__ atts,
                       float* __restrict__ attd) {
    int b = blockIdx.x, t = threadIdx.x;
    if (b < DIM) {
        float s = 0.f;
#pragma unroll
        for (int r = 0; r < 8; r++) s += B[b * 8 + r] * A[r * DIM + t];
        weff[b * DIM + t] = W[b * DIM + t] + LORA_SCALE * s;
    } else {
        int c = t & 31;
        float ss = 0.f, sd = 0.f;
#pragma unroll
        for (int r = 0; r < 4; r++) {
            ss += Bs[r] * As[r * CH + c];
            sd += Bd[r] * Ad[r * CH + c];
        }
        atts[t] = as_[t] + ATT_SCALE * ss;
        attd[t] = ad_[t] + ATT_SCALE * sd;
    }
}

// ---------------- 1xTF32 GEMM (round-12 inner loop) + cp.async double buffer -----
// Y[m][n] = sum_k X[m][k] * Wf[n][k];  fused per-head scores in epilogue.
#define BM 128
#define BN 64
#define KC 32
#define KPAD 36
#define ABUF (BM * KPAD)          // floats per A buffer
#define BBUF (BN * KPAD)          // floats per B buffer
#define GEMM_SMEM ((2 * ABUF + 2 * BBUF) * 4)   // 55296 bytes
__global__ void __launch_bounds__(256, 3) k_gemm(const float* __restrict__ X,
                                                 const float* __restrict__ Wf,
                                                 float* __restrict__ Y,
                                                 const float* __restrict__ atts,
                                                 const float* __restrict__ attd) {
    extern __shared__ float smem[];
    float* Asm = smem;                 // [2][BM][KPAD]
    float* Bsm = smem + 2 * ABUF;      // [2][BN][KPAD]
    const uint32_t sA = (uint32_t)__cvta_generic_to_shared(Asm);
    const uint32_t sB = (uint32_t)__cvta_generic_to_shared(Bsm);

    const int t = threadIdx.x;
    const int wid = t >> 5, lane = t & 31;
    const int warp_m = wid & 3, warp_n = wid >> 2;
    const int gid = lane >> 2, tq = lane & 3;
    const int m0 = blockIdx.y * BM, n0 = blockIdx.x * BN;
    const int h = blockIdx.x * 2 + warp_n;          // this warp's head
    const float4 z4 = make_float4(0.f, 0.f, 0.f, 0.f);

    // staging: A 2 threads/row (16 floats each -> 4 cp16), B 4 threads/row (8 floats -> 2 cp16)
    const int a_row = t >> 1, a_seg = t & 1;
    const int b_row = t >> 2, b_q = t & 3;
    const int gmA = m0 + a_row;
    const uint32_t aOK = (gmA < N_NODES) ? 16u : 0u;
    const float* gA = X + (size_t)gmA * DIM + a_seg * 16;
    const float* gB = Wf + (size_t)(n0 + b_row) * DIM;
    const uint32_t dA = sA + (a_row * KPAD + a_seg * 16) * 4;
    const uint32_t dB = sB + (b_row * KPAD + b_q * 4) * 4;

    float4 acc[2][4];
#pragma unroll
    for (int i = 0; i < 2; i++)
#pragma unroll
        for (int j = 0; j < 4; j++) acc[i][j] = z4;

#define STAGE(buf, k0)                                                        \
    {                                                                         \
        uint32_t da = dA + (buf) * (ABUF * 4);                                \
        uint32_t db = dB + (buf) * (BBUF * 4);                                \
        cp16(da + 0,  gA + (k0) + 0,  aOK);                                   \
        cp16(da + 16, gA + (k0) + 4,  aOK);                                   \
        cp16(da + 32, gA + (k0) + 8,  aOK);                                   \
        cp16(da + 48, gA + (k0) + 12, aOK);                                   \
        cp16(db,      gB + (k0) + b_q * 4,      16u);                         \
        cp16(db + 64, gB + (k0) + 16 + b_q * 4, 16u);                         \
    }

    STAGE(0, 0);
    cp_commit();

    const int NIT = DIM / KC;   // 8
    for (int it = 0; it < NIT; it++) {
        bool more = (it + 1 < NIT);
        if (more) {
            STAGE((it + 1) & 1, (it + 1) * KC);
            cp_commit();
            cp_wait<1>();
        } else {
            cp_wait<0>();
        }
        __syncthreads();
        const float* Ab = Asm + (it & 1) * ABUF;
        const float* Bb = Bsm + (it & 1) * BBUF;
#pragma unroll
        for (int kk = 0; kk < KC; kk += 8) {
            uint32_t bh[4][2];
#pragma unroll
            for (int nf = 0; nf < 4; nf++) {
                int col = warp_n * 32 + nf * 8 + gid;
                bh[nf][0] = f2tf32(Bb[col * KPAD + kk + tq]);
                bh[nf][1] = f2tf32(Bb[col * KPAD + kk + tq + 4]);
            }
#pragma unroll
            for (int mf = 0; mf < 2; mf++) {
                int rbse = warp_m * 32 + mf * 16;
                uint32_t ah0 = f2tf32(Ab[(rbse + gid) * KPAD + kk + tq]);
                uint32_t ah1 = f2tf32(Ab[(rbse + gid + 8) * KPAD + kk + tq]);
                uint32_t ah2 = f2tf32(Ab[(rbse + gid) * KPAD + kk + tq + 4]);
                uint32_t ah3 = f2tf32(Ab[(rbse + gid + 8) * KPAD + kk + tq + 4]);
#pragma unroll
                for (int nf = 0; nf < 4; nf++) {
                    mma_tf32(acc[mf][nf], ah0, ah1, ah2, ah3, bh[nf][0], bh[nf][1]);
                }
            }
        }
        __syncthreads();
    }

    // ---- epilogue: store Y tile + fused per-head attention scores ----
    const float* ath = atts + h * CH;
    const float* adh = attd + h * CH;
#pragma unroll
    for (int mf = 0; mf < 2; mf++) {
        int r0 = m0 + warp_m * 32 + mf * 16 + gid;
        int r1 = r0 + 8;
        float s0s = 0.f, s0d = 0.f, s1s = 0.f, s1d = 0.f;
#pragma unroll
        for (int nf = 0; nf < 4; nf++) {
            int c = nf * 8 + 2 * tq;
            float4 v = acc[mf][nf];
            float w0s = ath[c], w1s = ath[c + 1];
            float w0d = adh[c], w1d = adh[c + 1];
            s0s += v.x * w0s + v.y * w1s;
            s0d += v.x * w0d + v.y * w1d;
            s1s += v.z * w0s + v.w * w1s;
            s1d += v.z * w0d + v.w * w1d;
            int col = n0 + warp_n * 32 + c;
            if (r0 < N_NODES) *(float2*)(Y + (size_t)r0 * DIM + col) = make_float2(v.x, v.y);
            if (r1 < N_NODES) *(float2*)(Y + (size_t)r1 * DIM + col) = make_float2(v.z, v.w);
        }
#pragma unroll
        for (int o = 1; o < 4; o <<= 1) {
            s0s += __shfl_xor_sync(0xffffffffu, s0s, o);
            s0d += __shfl_xor_sync(0xffffffffu, s0d, o);
            s1s += __shfl_xor_sync(0xffffffffu, s1s, o);
            s1d += __shfl_xor_sync(0xffffffffu, s1d, o);
        }
        if (tq == 0) {
            if (r0 < N_NODES) { g_ssrc[r0 * HEADS + h] = s0s; g_sdst[r0 * HEADS + h] = s0d; }
            if (r1 < N_NODES) { g_ssrc[r1 * HEADS + h] = s1s; g_sdst[r1 * HEADS + h] = s1d; }
        }
    }
}

// ---------------- single-pass softmax + aggregation, 4x unrolled ----------------
template <int MODE>
__global__ void __launch_bounds__(256) k_aggr(const float* __restrict__ xp, float* __restrict__ out) {
    __shared__ float red[256];
    int n = blockIdx.x, t = threadIdx.x;
    int h = t >> 5, lane = t & 31;
    int beg = g_off[n], end = g_off[n + 1];
    float ssrc = g_ssrc[n * HEADS + h];
    const float* __restrict__ xph = xp + h * CH + lane;
    const float* __restrict__ sdh = g_sdst + h;

    float den = 0.f, acc = 0.f;
    int i = beg;
    for (; i + 4 <= end; i += 4) {
        int s0 = g_csrc[i + 0];
        int s1 = g_csrc[i + 1];
        int s2 = g_csrc[i + 2];
        int s3 = g_csrc[i + 3];
        float d0 = sdh[s0 * HEADS], d1 = sdh[s1 * HEADS];
        float d2 = sdh[s2 * HEADS], d3 = sdh[s3 * HEADS];
        float x0 = xph[s0 * DIM], x1 = xph[s1 * DIM];
        float x2 = xph[s2 * DIM], x3 = xph[s3 * DIM];
        float a0 = ssrc + d0, a1 = ssrc + d1, a2 = ssrc + d2, a3 = ssrc + d3;
        a0 = fminf(fmaxf(a0, NEG_SLOPE * a0), 80.f);
        a1 = fminf(fmaxf(a1, NEG_SLOPE * a1), 80.f);
        a2 = fminf(fmaxf(a2, NEG_SLOPE * a2), 80.f);
        a3 = fminf(fmaxf(a3, NEG_SLOPE * a3), 80.f);
        float w0 = __expf(a0), w1 = __expf(a1), w2 = __expf(a2), w3 = __expf(a3);
        den += (w0 + w1) + (w2 + w3);
        acc += w0 * x0 + w1 * x1 + w2 * x2 + w3 * x3;
    }
    for (; i < end; i++) {
        int s = g_csrc[i];
        float a = ssrc + sdh[s * HEADS];
        a = fminf(fmaxf(a, NEG_SLOPE * a), 80.f);
        float w = __expf(a);
        den += w;
        acc += w * xph[s * DIM];
    }
    float r = acc / den;
    if (MODE == 0) {
        out[n * DIM + t] = (r > 0.f) ? r : (__expf(r) - 1.0f);  // ELU
    } else {
        red[t] = r;
        __syncthreads();
        if (t < CH) {
            float s = 0.f;
#pragma unroll
            for (int hh = 0; hh < HEADS; hh++) s += red[hh * CH + t];
            out[n * CH + t] = s * 0.125f;
        }
    }
}

// ---------------- side stream / events (created before harness checkpoints) ------
namespace {
struct StreamInit {
    cudaStream_t s2;
    cudaEvent_t evFork, evJoin;
    StreamInit() {
        cudaStreamCreateWithFlags(&s2, cudaStreamNonBlocking);
        cudaEventCreateWithFlags(&evFork, cudaEventDisableTiming);
        cudaEventCreateWithFlags(&evJoin, cudaEventDisableTiming);
        cudaFuncSetAttribute(k_gemm, cudaFuncAttributeMaxDynamicSharedMemorySize, GEMM_SMEM);
    }
};
StreamInit g_si;
}

// ---------------- host launcher ----------------
// Enqueue order keeps k_gemm as the 4th kernel enqueued (ncu capture slot).
extern "C" void kernel_launch(void* const* d_in, const int* in_sizes, int n_in,
                              void* d_out, int out_size) {
    const float* x  = (const float*)d_in[0];
    const void*  ei = d_in[1];

    float *xp, *act, *weff0, *weff1, *atts0, *attd0, *atts1, *attd1;
    cudaGetSymbolAddress((void**)&xp, g_xp);
    cudaGetSymbolAddress((void**)&act, g_act);
    cudaGetSymbolAddress((void**)&weff0, g_weff0);
    cudaGetSymbolAddress((void**)&weff1, g_weff1);
    cudaGetSymbolAddress((void**)&atts0, g_atts0);
    cudaGetSymbolAddress((void**)&attd0, g_attd0);
    cudaGetSymbolAddress((void**)&atts1, g_atts1);
    cudaGetSymbolAddress((void**)&attd1, g_attd1);

    cudaStream_t s2 = g_si.s2;

    // fork side stream off the (capturing) default stream
    cudaEventRecord(g_si.evFork, 0);
    cudaStreamWaitEvent(s2, g_si.evFork, 0);

    // enqueue #1, #2 (side stream)
    k_prep<<<DIM + 1, DIM, 0, s2>>>(
        (const float*)d_in[11], (const float*)d_in[12], (const float*)d_in[13],
        (const float*)d_in[14], (const float*)d_in[15],
        (const float*)d_in[16], (const float*)d_in[17],
        (const float*)d_in[18], (const float*)d_in[19],
        weff1, atts1, attd1);
    k_detect<<<40, 256, 0, s2>>>(ei);

    dim3 gg(DIM / BN, (N_NODES + BM - 1) / BM);

    // enqueue #3, #4 (main stream) — #4 = k_gemm gets the ncu capture
    k_prep<<<DIM + 1, DIM>>>(
        (const float*)d_in[2], (const float*)d_in[3], (const float*)d_in[4],
        (const float*)d_in[5], (const float*)d_in[6],
        (const float*)d_in[7], (const float*)d_in[8],
        (const float*)d_in[9], (const float*)d_in[10],
        weff0, atts0, attd0);
    k_gemm<<<gg, 256, GEMM_SMEM>>>(x, weff0, xp, atts0, attd0);

    // enqueue #5..#7 (side stream, continues after detect)
    k_hist<<<(N_EDGES + 255) / 256, 256, 0, s2>>>(ei);
    k_scan<<<1, 1024, 0, s2>>>();
    k_scatter<<<(E_TOT + 255) / 256, 256, 0, s2>>>(ei);
    cudaEventRecord(g_si.evJoin, s2);

    // join: aggr0 needs CSR; gemm1 needs weff1
    cudaStreamWaitEvent(0, g_si.evJoin, 0);

    k_aggr<0><<<N_NODES, 256>>>(xp, act);
    k_gemm<<<gg, 256, GEMM_SMEM>>>(act, weff1, xp, atts1, attd1);
    k_aggr<1><<<N_NODES, 256>>>(xp, (float*)d_out);
}